// round 6
// baseline (speedup 1.0000x reference)
#include <cuda_runtime.h>

#define FULL 0xffffffffu

// theta-derived tables. Amp index I: bit q = qubit q (q0..q4 reg bits, q5..q7 lane bits).
// g_d0x[comp*256 + I]  : comp0 -> cos(phi_I), comp1 -> sin(phi_I)   (D0 = RZ(phi) layer0)
// g_d1ab[comp*256 + I] : (cos(psi_I), comp? +sin : -sin)            (D1 = perm-conj om0 * phi1)
__device__ float2 g_ry[16];
__device__ __align__(16) float  g_d0x[512];
__device__ __align__(16) float2 g_d1ab[512];

__global__ void precompute_kernel(const float* __restrict__ theta) {
    int I = threadIdx.x;          // 0..255
    if (I < 16) {
        int layer = I >> 3, q = I & 7;
        float th = theta[layer * 24 + q * 3 + 1];
        float s, c;
        sincosf(0.5f * th, &s, &c);
        g_ry[I] = make_float2(c, s);
    }
    // D0 angle: RZ(phi) layer0, bit=0 -> -phi/2, bit=1 -> +phi/2
    float a0 = 0.0f;
    #pragma unroll
    for (int q = 0; q < 8; q++) {
        float phi = theta[q * 3 + 0];
        a0 += ((I >> q) & 1) ? 0.5f * phi : -0.5f * phi;
    }
    float s0, c0;
    sincosf(a0, &s0, &c0);
    g_d0x[I]       = c0;   // comp 0 (real)
    g_d0x[256 + I] = s0;   // comp 1 (imag)

    // D1(K) = e^{i psi_K}, psi = Om0(src(K)) + Phi1(K), src(K) = K ^ ((K & 0x7F) << 1)
    int src = I ^ ((I & 0x7F) << 1);
    float a1 = 0.0f;
    #pragma unroll
    for (int q = 0; q < 8; q++) {
        float om0  = theta[q * 3 + 2];
        float phi1 = theta[24 + q * 3 + 0];
        a1 += ((src >> q) & 1) ? 0.5f * om0  : -0.5f * om0;
        a1 += ((I   >> q) & 1) ? 0.5f * phi1 : -0.5f * phi1;
    }
    float s1, c1;
    sincosf(a1, &s1, &c1);
    // comp0: new_c = cos*pc - sin*ps ; comp1: new_s = cos*ps_same + sin*pc_other
    g_d1ab[I]       = make_float2(c1, -s1);
    g_d1ab[256 + I] = make_float2(c1,  s1);
    // RZ(om) of layer 1 dropped: no effect on probabilities.
}

// In-place CNOT-perm step fused with D1, scalar component version.
// new[DST] = A[DST]*old_samecomp[src] + B[DST]*old_othercomp[src]
#define PERM_STEP(DST, SRC) { \
    int gl_ = sgl ^ (((DST) >> 4) & 1); \
    float pc_ = __shfl_sync(FULL, v[SRC], gl_); \
    float ps_ = __shfl_sync(FULL, v[SRC], gl_ ^ 8); \
    float2 d_ = d1p[DST]; \
    v[DST] = fmaf(d_.y, ps_, d_.x * pc_); }

#define PERM_LAST(DST) { \
    int gl_ = sgl ^ (((DST) >> 4) & 1); \
    float pc_ = __shfl_sync(FULL, tv_, gl_); \
    float ps_ = __shfl_sync(FULL, tv_, gl_ ^ 8); \
    float2 d_ = d1p[DST]; \
    v[DST] = fmaf(d_.y, ps_, d_.x * pc_); }

__global__ void __launch_bounds__(256, 3)
qsim_kernel(const float* __restrict__ x, float* __restrict__ out, int batch) {
    int gw   = (int)((blockIdx.x * blockDim.x + threadIdx.x) >> 5);
    int lane = threadIdx.x & 31;
    int g    = lane & 7;           // lane-qubit bits (qubits 5,6,7)
    int comp = (lane >> 3) & 1;    // 0 = real component, 1 = imag component
    int s    = (lane >> 4) & 1;    // sample within warp
    int sample = gw * 2 + s;
    if (gw * 2 >= batch) return;
    int sidx = sample < batch ? sample : batch - 1;

    // ---- angle encoding ----
    float xv = x[sidx * 8 + g];
    xv = fminf(1.0f, fmaxf(-1.0f, xv));
    float sv, cv;
    sincospif(0.5f * xv, &sv, &cv);

    int grp = lane & 0x18;         // (sample, comp) lane-group base
    float cq[8], sq[8];
    #pragma unroll
    for (int q = 0; q < 8; q++) {
        cq[q] = __shfl_sync(FULL, cv, grp | q);
        sq[q] = __shfl_sync(FULL, sv, grp | q);
    }
    // lane factor over qubits 5,6,7 (g bits 0..2)
    float lf = ((g & 1) ? sq[5] : cq[5]) * ((g & 2) ? sq[6] : cq[6])
             * ((g & 4) ? sq[7] : cq[7]);

    // real product over reg qubits 0..4, then component of D0
    float t1a = lf * cq[0], t1b = lf * sq[0];
    float t2[4], t3[8], t4[16], v[32];
    #pragma unroll
    for (int j = 0; j < 4; j++)
        t2[j] = ((j & 1) ? t1b : t1a) * ((j & 2) ? sq[1] : cq[1]);
    #pragma unroll
    for (int j = 0; j < 8; j++)
        t3[j] = t2[j & 3] * ((j & 4) ? sq[2] : cq[2]);
    #pragma unroll
    for (int j = 0; j < 16; j++)
        t4[j] = t3[j & 7] * ((j & 8) ? sq[3] : cq[3]);
    const float* d0p = g_d0x + comp * 256 + g * 32;
    #pragma unroll
    for (int j = 0; j < 32; j++)
        v[j] = t4[j & 15] * ((j & 16) ? sq[4] : cq[4]) * d0p[j];

    const int sgl = grp | (g ^ ((g & 3) << 1));   // perm source lane (before j4 xor)
    const float2* d1p = g_d1ab + comp * 256 + g * 32;

    // ---- two layers of REAL RY gates + fused perm/diagonal ----
    #pragma unroll
    for (int layer = 0; layer < 2; layer++) {
        #pragma unroll
        for (int q = 0; q < 5; q++) {          // reg-qubit gates (in-lane, real 2x2)
            float2 gg = g_ry[layer * 8 + q];
            float cg = gg.x, sg2 = gg.y;
            int m = 1 << q;
            #pragma unroll
            for (int j0 = 0; j0 < 32; j0++) {
                if (j0 & m) continue;
                int j1 = j0 | m;
                float b0 = v[j0], b1 = v[j1];
                v[j0] = fmaf(-sg2, b1, cg * b0);
                v[j1] = fmaf( sg2, b0, cg * b1);
            }
        }
        #pragma unroll
        for (int q = 5; q < 8; q++) {          // lane-qubit gates (1 shfl per reg!)
            float2 gg = g_ry[layer * 8 + q];
            float cg = gg.x;
            int pb = 1 << (q - 5);
            float ss = (g & pb) ? gg.y : -gg.y;
            #pragma unroll
            for (int j = 0; j < 32; j++) {
                float pr = __shfl_xor_sync(FULL, v[j], pb);
                v[j] = fmaf(ss, pr, cg * v[j]);
            }
        }

        if (layer == 0) {
            // CNOT chain: new[I] = D1[I] * old[src(I)], src = I^((I&0x7F)<<1).
            // Reg part sigma(j) = j^((j&15)<<1), walked in-place along cycles.
            PERM_STEP(0, 0)
            PERM_STEP(16, 16)
            { float tv_ = v[8];
              PERM_STEP(8, 24) PERM_LAST(24) }
            { float tv_ = v[2];
              PERM_STEP(2, 6) PERM_STEP(6, 10) PERM_STEP(10, 30) PERM_LAST(30) }
            { float tv_ = v[4];
              PERM_STEP(4, 12) PERM_STEP(12, 20) PERM_STEP(20, 28) PERM_LAST(28) }
            { float tv_ = v[14];
              PERM_STEP(14, 18) PERM_STEP(18, 22) PERM_STEP(22, 26) PERM_LAST(26) }
            { float tv_ = v[1];
              PERM_STEP(1, 3) PERM_STEP(3, 5) PERM_STEP(5, 15) PERM_STEP(15, 17)
              PERM_STEP(17, 19) PERM_STEP(19, 21) PERM_STEP(21, 31) PERM_LAST(31) }
            { float tv_ = v[7];
              PERM_STEP(7, 9) PERM_STEP(9, 27) PERM_STEP(27, 13) PERM_STEP(13, 23)
              PERM_STEP(23, 25) PERM_STEP(25, 11) PERM_STEP(11, 29) PERM_LAST(29) }
        }
        // layer 1: om-diag dropped; its CNOT chain folded into Walsh below.
    }

    // ---- measurement ----
    // p_I = c_I^2 + s_I^2: each comp half contributes v^2; the cross-comp sum
    // folds into the xor-8 butterfly step below.
    float p[32];
    #pragma unroll
    for (int j = 0; j < 32; j++)
        p[j] = v[j] * v[j];

    // signed prefix-parity cascade over reg bits 0..4 -> u0..u4
    float c1[16], c2[8], c3[4], c4[2];
    #pragma unroll
    for (int k = 0; k < 16; k++) c1[k] = p[2 * k] - p[2 * k + 1];
    #pragma unroll
    for (int k = 0; k < 8; k++)  c2[k] = c1[2 * k] - c1[2 * k + 1];
    #pragma unroll
    for (int k = 0; k < 4; k++)  c3[k] = c2[2 * k] - c2[2 * k + 1];
    c4[0] = c3[0] - c3[1]; c4[1] = c3[2] - c3[3];
    float u0 = 0.0f, u1 = 0.0f, u2 = 0.0f;
    #pragma unroll
    for (int k = 0; k < 16; k++) u0 += c1[k];
    #pragma unroll
    for (int k = 0; k < 8; k++)  u1 += c2[k];
    #pragma unroll
    for (int k = 0; k < 4; k++)  u2 += c3[k];
    float u3 = c4[0] + c4[1];
    float u4 = c4[0] - c4[1];

    // butterfly over g bits (Walsh for u4) then comp bit (plain; completes c^2+s^2)
    #pragma unroll
    for (int d = 1; d < 8; d <<= 1) {
        u0 += __shfl_xor_sync(FULL, u0, d);
        u1 += __shfl_xor_sync(FULL, u1, d);
        u2 += __shfl_xor_sync(FULL, u2, d);
        u3 += __shfl_xor_sync(FULL, u3, d);
        float pv = __shfl_xor_sync(FULL, u4, d);
        u4 = (g & d) ? (pv - u4) : (u4 + pv);
    }
    u0 += __shfl_xor_sync(FULL, u0, 8);
    u1 += __shfl_xor_sync(FULL, u1, 8);
    u2 += __shfl_xor_sync(FULL, u2, 8);
    u3 += __shfl_xor_sync(FULL, u3, 8);
    u4 += __shfl_xor_sync(FULL, u4, 8);

    if (sample < batch && comp == 0) {
        float* o = out + sample * 8;
        if (g == 0) { o[0] = u0; o[1] = u1; o[2] = u2; o[3] = u3; }
        if ((g & (g + 1)) == 0)            // g = 0,1,3,7 -> qubits 4,5,6,7
            o[4 + __popc(g)] = u4;
    }
}

extern "C" void kernel_launch(void* const* d_in, const int* in_sizes, int n_in,
                              void* d_out, int out_size) {
    const float* inputs = (const float*)d_in[0];   // [16384, 8] f32
    const float* theta  = (const float*)d_in[1];   // [2, 8, 3]  f32
    float* out = (float*)d_out;                    // [16384, 8] f32

    int batch = in_sizes[0] / 8;

    precompute_kernel<<<1, 256>>>(theta);

    int warps = (batch + 1) / 2;              // 2 samples per warp
    int threads = 256;                        // 8 warps / block
    int blocks = (warps * 32 + threads - 1) / threads;
    qsim_kernel<<<blocks, threads>>>(inputs, out, batch);
}

// round 7
// speedup vs baseline: 1.3574x; 1.3574x over previous
#include <cuda_runtime.h>

#define FULL 0xffffffffu

// theta-derived tables (sample-independent). Amp index I: bit q = qubit q.
// Layout in qsim: I = (g<<4)|j, g = lane&15 (qubits 4..7), j = reg idx (qubits 0..3).
__device__ float2 g_ry[16];
__device__ __align__(16) float2 g_d0[256];
__device__ __align__(16) float2 g_d1[256];

__global__ void precompute_kernel(const float* __restrict__ theta) {
    int I = threadIdx.x;          // 0..255
    if (I < 16) {
        int layer = I >> 3, q = I & 7;
        float th = theta[layer * 24 + q * 3 + 1];
        float s, c;
        sincosf(0.5f * th, &s, &c);
        g_ry[I] = make_float2(c, s);
    }
    // D0: RZ(phi) layer 0: bit=0 -> e^{-i phi/2}, bit=1 -> e^{+i phi/2}
    float a0 = 0.0f;
    #pragma unroll
    for (int q = 0; q < 8; q++) {
        float phi = theta[q * 3 + 0];
        a0 += ((I >> q) & 1) ? 0.5f * phi : -0.5f * phi;
    }
    float sr, cr;
    sincosf(a0, &sr, &cr);
    g_d0[I] = make_float2(cr, sr);

    // D1(K) = e^{i Om0(src(K))} * e^{i Phi1(K)}, src(K) = K ^ ((K & 0x7F) << 1)
    int src = I ^ ((I & 0x7F) << 1);
    float a1 = 0.0f;
    #pragma unroll
    for (int q = 0; q < 8; q++) {
        float om0  = theta[q * 3 + 2];
        float phi1 = theta[24 + q * 3 + 0];
        a1 += ((src >> q) & 1) ? 0.5f * om0  : -0.5f * om0;
        a1 += ((I   >> q) & 1) ? 0.5f * phi1 : -0.5f * phi1;
    }
    sincosf(a1, &sr, &cr);
    g_d1[I] = make_float2(cr, sr);
    // RZ(om) of layer 1 dropped: no effect on probabilities.
}

// In-place CNOT-perm step fused with D1: new[DST] = D1[DST] * old[SRC]@srclane
#define PERM_STEP(DST, SRC) { \
    int sl_ = slA ^ (((DST) >> 3) & 1); \
    float pr_ = __shfl_sync(FULL, ar[SRC], sl_); \
    float pi_ = __shfl_sync(FULL, ai[SRC], sl_); \
    float2 d_ = d1p[DST]; \
    ar[DST] = d_.x * pr_ - d_.y * pi_; \
    ai[DST] = d_.x * pi_ + d_.y * pr_; }

#define PERM_LAST(DST) { \
    int sl_ = slA ^ (((DST) >> 3) & 1); \
    float pr_ = __shfl_sync(FULL, tr_, sl_); \
    float pi_ = __shfl_sync(FULL, ti_, sl_); \
    float2 d_ = d1p[DST]; \
    ar[DST] = d_.x * pr_ - d_.y * pi_; \
    ai[DST] = d_.x * pi_ + d_.y * pr_; }

__global__ void __launch_bounds__(256)
qsim_kernel(const float* __restrict__ x, float* __restrict__ out, int batch) {
    int gw   = (int)((blockIdx.x * blockDim.x + threadIdx.x) >> 5);
    int lane = threadIdx.x & 31;
    int g    = lane & 15;          // lane-qubit bits (qubits 4..7)
    int base = lane & 16;          // sample selector
    int sample = gw * 2 + (lane >> 4);
    if (gw * 2 >= batch) return;
    int sidx = sample < batch ? sample : batch - 1;

    // ---- angle encoding ----
    float xv = x[sidx * 8 + (g & 7)];
    xv = fminf(1.0f, fmaxf(-1.0f, xv));
    float sv, cv;
    sincospif(0.5f * xv, &sv, &cv);

    float cq[8], sq[8];
    #pragma unroll
    for (int q = 0; q < 8; q++) {
        cq[q] = __shfl_sync(FULL, cv, base | q);
        sq[q] = __shfl_sync(FULL, sv, base | q);
    }
    // lane factor over qubits 4..7 (g bits 0..3)
    float lf = ((g & 1) ? sq[4] : cq[4]) * ((g & 2) ? sq[5] : cq[5])
             * ((g & 4) ? sq[6] : cq[6]) * ((g & 8) ? sq[7] : cq[7]);

    // real product over reg qubits 0..3
    float a0v = lf * cq[0], a1v = lf * sq[0];
    float t2[4], t3[8], amp[16];
    #pragma unroll
    for (int j = 0; j < 4; j++)
        t2[j] = ((j & 1) ? a1v : a0v) * ((j & 2) ? sq[1] : cq[1]);
    #pragma unroll
    for (int j = 0; j < 8; j++)
        t3[j] = t2[j & 3] * ((j & 4) ? sq[2] : cq[2]);
    #pragma unroll
    for (int j = 0; j < 16; j++)
        amp[j] = t3[j & 7] * ((j & 8) ? sq[3] : cq[3]);

    // apply D0 (phi-diagonal of layer 0)
    const float4* d0v = reinterpret_cast<const float4*>(g_d0) + g * 8;
    float ar[16], ai[16];
    #pragma unroll
    for (int jj = 0; jj < 8; jj++) {
        float4 d = d0v[jj];
        int j0 = 2 * jj, j1 = j0 + 1;
        ar[j0] = amp[j0] * d.x; ai[j0] = amp[j0] * d.y;
        ar[j1] = amp[j1] * d.z; ai[j1] = amp[j1] * d.w;
    }

    // CNOT perm: src lane (4-bit) = g ^ ((g&7)<<1), xor'd with dst reg bit 3
    const int slA = base | (g ^ ((g & 7) << 1));
    const float2* d1p = g_d1 + (g << 4);

    // ---- two layers of real RY gates + fused perm/diagonal ----
    #pragma unroll
    for (int layer = 0; layer < 2; layer++) {
        #pragma unroll
        for (int q = 0; q < 4; q++) {           // reg-qubit gates (in-lane)
            float2 gg = g_ry[layer * 8 + q];
            float cg = gg.x, sgv = gg.y;
            int m = 1 << q;
            #pragma unroll
            for (int j0 = 0; j0 < 16; j0++) {
                if (j0 & m) continue;
                int j1 = j0 | m;
                float b0r = ar[j0], b0i = ai[j0];
                float b1r = ar[j1], b1i = ai[j1];
                ar[j0] = fmaf(-sgv, b1r, cg * b0r);
                ai[j0] = fmaf(-sgv, b1i, cg * b0i);
                ar[j1] = fmaf( sgv, b0r, cg * b1r);
                ai[j1] = fmaf( sgv, b0i, cg * b1i);
            }
        }
        #pragma unroll
        for (int q = 4; q < 8; q++) {           // lane-qubit gates
            float2 gg = g_ry[layer * 8 + q];
            float cg = gg.x;
            int pb = 1 << (q - 4);
            float ss = (g & pb) ? gg.y : -gg.y;
            #pragma unroll
            for (int j = 0; j < 16; j++) {
                float pr = __shfl_xor_sync(FULL, ar[j], pb);
                float pi = __shfl_xor_sync(FULL, ai[j], pb);
                ar[j] = fmaf(ss, pr, cg * ar[j]);
                ai[j] = fmaf(ss, pi, cg * ai[j]);
            }
        }

        if (layer == 0) {
            // CNOT chain: new[I] = D1[I]*old[src(I)], src = I^((I&0x7F)<<1).
            // Reg part sigma(j) = j^((j&7)<<1): cycles (0)(8)(4 12)(1 3 5 15)(2 6 10 14)(7 9 11 13)
            PERM_STEP(0, 0)
            PERM_STEP(8, 8)
            { float tr_ = ar[4], ti_ = ai[4];
              PERM_STEP(4, 12) PERM_LAST(12) }
            { float tr_ = ar[1], ti_ = ai[1];
              PERM_STEP(1, 3) PERM_STEP(3, 5) PERM_STEP(5, 15) PERM_LAST(15) }
            { float tr_ = ar[2], ti_ = ai[2];
              PERM_STEP(2, 6) PERM_STEP(6, 10) PERM_STEP(10, 14) PERM_LAST(14) }
            { float tr_ = ar[7], ti_ = ai[7];
              PERM_STEP(7, 9) PERM_STEP(9, 11) PERM_STEP(11, 13) PERM_LAST(13) }
        }
        // layer 1: om-diag dropped; its CNOT chain folded into Walsh below.
    }

    // ---- measurement: e_q = sum_I (-1)^{parity(I & (2^{q+1}-1))} p_I ----
    float p[16];
    #pragma unroll
    for (int j = 0; j < 16; j++)
        p[j] = ar[j] * ar[j] + ai[j] * ai[j];

    // signed prefix-parity cascade over reg bits 0..3
    float c1[8], c2[4], c3[2];
    #pragma unroll
    for (int k = 0; k < 8; k++) c1[k] = p[2 * k] - p[2 * k + 1];
    #pragma unroll
    for (int k = 0; k < 4; k++) c2[k] = c1[2 * k] - c1[2 * k + 1];
    c3[0] = c2[0] - c2[1]; c3[1] = c2[2] - c2[3];
    float u0 = 0.0f, u1 = 0.0f;
    #pragma unroll
    for (int k = 0; k < 8; k++) u0 += c1[k];
    #pragma unroll
    for (int k = 0; k < 4; k++) u1 += c2[k];
    float u2 = c3[0] + c3[1];
    float t  = c3[0] - c3[1];     // full reg-parity term, seeds e3..e7

    // butterflies over g bits (within 16-lane sample group):
    // plain sums for u0..u2 (e0..e2); Walsh for t (e3..e7 at g=0,1,3,7,15)
    #pragma unroll
    for (int d = 1; d < 16; d <<= 1) {
        u0 += __shfl_xor_sync(FULL, u0, d);
        u1 += __shfl_xor_sync(FULL, u1, d);
        u2 += __shfl_xor_sync(FULL, u2, d);
        float pv = __shfl_xor_sync(FULL, t, d);
        t = (g & d) ? (pv - t) : (t + pv);
    }

    if (sample < batch) {
        float* o = out + sample * 8;
        if (g == 0) { o[0] = u0; o[1] = u1; o[2] = u2; o[3] = t; }
        else if ((g & (g + 1)) == 0)     // g = 1,3,7,15 -> qubits 4,5,6,7
            o[3 + __popc(g)] = t;
    }
}

extern "C" void kernel_launch(void* const* d_in, const int* in_sizes, int n_in,
                              void* d_out, int out_size) {
    const float* inputs = (const float*)d_in[0];   // [16384, 8] f32
    const float* theta  = (const float*)d_in[1];   // [2, 8, 3]  f32
    float* out = (float*)d_out;                    // [16384, 8] f32

    int batch = in_sizes[0] / 8;

    precompute_kernel<<<1, 256>>>(theta);

    int warps = (batch + 1) / 2;              // 2 samples per warp
    int threads = 256;                        // 8 warps / block
    int blocks = (warps * 32 + threads - 1) / threads;
    qsim_kernel<<<blocks, threads>>>(inputs, out, batch);
}

// round 8
// speedup vs baseline: 2.3008x; 1.6951x over previous
#include <cuda_runtime.h>

#define FULL 0xffffffffu

// theta-derived tables (sample-independent). Amp index I: bit q = qubit q.
// Layout in qsim: I = (g<<4)|j, g = lane&15 (qubits 4..7), j = reg idx (qubits 0..3).
// Tables are stored TRANSPOSED as [j*16 + g] so that for a fixed j (compile-time
// constant in the unrolled loops) the 16 lanes read 16 consecutive float2s
// (128 bytes, 1 wavefront) instead of a 128B-strided scatter.
__device__ float2 g_ry[16];
__device__ __align__(16) float2 g_d0t[256];   // [j*16 + g]
__device__ __align__(16) float2 g_d1t[256];   // [j*16 + g]

__global__ void precompute_kernel(const float* __restrict__ theta) {
    int I = threadIdx.x;          // amp index 0..255
    if (I < 16) {
        int layer = I >> 3, q = I & 7;
        float th = theta[layer * 24 + q * 3 + 1];
        float s, c;
        sincosf(0.5f * th, &s, &c);
        g_ry[I] = make_float2(c, s);
    }
    int tslot = (I & 15) * 16 + (I >> 4);   // transposed slot for this amp index

    // D0: RZ(phi) layer 0: bit=0 -> e^{-i phi/2}, bit=1 -> e^{+i phi/2}
    float a0 = 0.0f;
    #pragma unroll
    for (int q = 0; q < 8; q++) {
        float phi = theta[q * 3 + 0];
        a0 += ((I >> q) & 1) ? 0.5f * phi : -0.5f * phi;
    }
    float sr, cr;
    sincosf(a0, &sr, &cr);
    g_d0t[tslot] = make_float2(cr, sr);

    // D1(K) = e^{i Om0(src(K))} * e^{i Phi1(K)}, src(K) = K ^ ((K & 0x7F) << 1)
    int src = I ^ ((I & 0x7F) << 1);
    float a1 = 0.0f;
    #pragma unroll
    for (int q = 0; q < 8; q++) {
        float om0  = theta[q * 3 + 2];
        float phi1 = theta[24 + q * 3 + 0];
        a1 += ((src >> q) & 1) ? 0.5f * om0  : -0.5f * om0;
        a1 += ((I   >> q) & 1) ? 0.5f * phi1 : -0.5f * phi1;
    }
    sincosf(a1, &sr, &cr);
    g_d1t[tslot] = make_float2(cr, sr);
    // RZ(om) of layer 1 dropped: no effect on probabilities.
}

// In-place CNOT-perm step fused with D1: new[DST] = D1[DST] * old[SRC]@srclane
// d1p = g_d1t + g, so d1p[DST*16] is a fully coalesced per-lane load.
#define PERM_STEP(DST, SRC) { \
    int sl_ = slA ^ (((DST) >> 3) & 1); \
    float pr_ = __shfl_sync(FULL, ar[SRC], sl_); \
    float pi_ = __shfl_sync(FULL, ai[SRC], sl_); \
    float2 d_ = d1p[(DST) * 16]; \
    ar[DST] = d_.x * pr_ - d_.y * pi_; \
    ai[DST] = d_.x * pi_ + d_.y * pr_; }

#define PERM_LAST(DST) { \
    int sl_ = slA ^ (((DST) >> 3) & 1); \
    float pr_ = __shfl_sync(FULL, tr_, sl_); \
    float pi_ = __shfl_sync(FULL, ti_, sl_); \
    float2 d_ = d1p[(DST) * 16]; \
    ar[DST] = d_.x * pr_ - d_.y * pi_; \
    ai[DST] = d_.x * pi_ + d_.y * pr_; }

__global__ void __launch_bounds__(256)
qsim_kernel(const float* __restrict__ x, float* __restrict__ out, int batch) {
    int gw   = (int)((blockIdx.x * blockDim.x + threadIdx.x) >> 5);
    int lane = threadIdx.x & 31;
    int g    = lane & 15;          // lane-qubit bits (qubits 4..7)
    int base = lane & 16;          // sample selector
    int sample = gw * 2 + (lane >> 4);
    if (gw * 2 >= batch) return;
    int sidx = sample < batch ? sample : batch - 1;

    // ---- angle encoding ----
    float xv = x[sidx * 8 + (g & 7)];
    xv = fminf(1.0f, fmaxf(-1.0f, xv));
    float sv, cv;
    sincospif(0.5f * xv, &sv, &cv);

    float cq[8], sq[8];
    #pragma unroll
    for (int q = 0; q < 8; q++) {
        cq[q] = __shfl_sync(FULL, cv, base | q);
        sq[q] = __shfl_sync(FULL, sv, base | q);
    }
    // lane factor over qubits 4..7 (g bits 0..3)
    float lf = ((g & 1) ? sq[4] : cq[4]) * ((g & 2) ? sq[5] : cq[5])
             * ((g & 4) ? sq[6] : cq[6]) * ((g & 8) ? sq[7] : cq[7]);

    // real product over reg qubits 0..3
    float a0v = lf * cq[0], a1v = lf * sq[0];
    float t2[4], t3[8], amp[16];
    #pragma unroll
    for (int j = 0; j < 4; j++)
        t2[j] = ((j & 1) ? a1v : a0v) * ((j & 2) ? sq[1] : cq[1]);
    #pragma unroll
    for (int j = 0; j < 8; j++)
        t3[j] = t2[j & 3] * ((j & 4) ? sq[2] : cq[2]);
    #pragma unroll
    for (int j = 0; j < 16; j++)
        amp[j] = t3[j & 7] * ((j & 8) ? sq[3] : cq[3]);

    // apply D0 (phi-diagonal of layer 0) -- coalesced transposed loads
    const float2* d0p = g_d0t + g;
    float ar[16], ai[16];
    #pragma unroll
    for (int j = 0; j < 16; j++) {
        float2 d = d0p[j * 16];
        ar[j] = amp[j] * d.x;
        ai[j] = amp[j] * d.y;
    }

    // CNOT perm: src lane (4-bit) = g ^ ((g&7)<<1), xor'd with dst reg bit 3
    const int slA = base | (g ^ ((g & 7) << 1));
    const float2* d1p = g_d1t + g;

    // ---- two layers of real RY gates + fused perm/diagonal ----
    #pragma unroll
    for (int layer = 0; layer < 2; layer++) {
        #pragma unroll
        for (int q = 0; q < 4; q++) {           // reg-qubit gates (in-lane)
            float2 gg = g_ry[layer * 8 + q];
            float cg = gg.x, sgv = gg.y;
            int m = 1 << q;
            #pragma unroll
            for (int j0 = 0; j0 < 16; j0++) {
                if (j0 & m) continue;
                int j1 = j0 | m;
                float b0r = ar[j0], b0i = ai[j0];
                float b1r = ar[j1], b1i = ai[j1];
                ar[j0] = fmaf(-sgv, b1r, cg * b0r);
                ai[j0] = fmaf(-sgv, b1i, cg * b0i);
                ar[j1] = fmaf( sgv, b0r, cg * b1r);
                ai[j1] = fmaf( sgv, b0i, cg * b1i);
            }
        }
        #pragma unroll
        for (int q = 4; q < 8; q++) {           // lane-qubit gates
            float2 gg = g_ry[layer * 8 + q];
            float cg = gg.x;
            int pb = 1 << (q - 4);
            float ss = (g & pb) ? gg.y : -gg.y;
            #pragma unroll
            for (int j = 0; j < 16; j++) {
                float pr = __shfl_xor_sync(FULL, ar[j], pb);
                float pi = __shfl_xor_sync(FULL, ai[j], pb);
                ar[j] = fmaf(ss, pr, cg * ar[j]);
                ai[j] = fmaf(ss, pi, cg * ai[j]);
            }
        }

        if (layer == 0) {
            // CNOT chain: new[I] = D1[I]*old[src(I)], src = I^((I&0x7F)<<1).
            // Reg part sigma(j) = j^((j&7)<<1): cycles (0)(8)(4 12)(1 3 5 15)(2 6 10 14)(7 9 11 13)
            PERM_STEP(0, 0)
            PERM_STEP(8, 8)
            { float tr_ = ar[4], ti_ = ai[4];
              PERM_STEP(4, 12) PERM_LAST(12) }
            { float tr_ = ar[1], ti_ = ai[1];
              PERM_STEP(1, 3) PERM_STEP(3, 5) PERM_STEP(5, 15) PERM_LAST(15) }
            { float tr_ = ar[2], ti_ = ai[2];
              PERM_STEP(2, 6) PERM_STEP(6, 10) PERM_STEP(10, 14) PERM_LAST(14) }
            { float tr_ = ar[7], ti_ = ai[7];
              PERM_STEP(7, 9) PERM_STEP(9, 11) PERM_STEP(11, 13) PERM_LAST(13) }
        }
        // layer 1: om-diag dropped; its CNOT chain folded into Walsh below.
    }

    // ---- measurement: e_q = sum_I (-1)^{parity(I & (2^{q+1}-1))} p_I ----
    float p[16];
    #pragma unroll
    for (int j = 0; j < 16; j++)
        p[j] = ar[j] * ar[j] + ai[j] * ai[j];

    // signed prefix-parity cascade over reg bits 0..3
    float c1[8], c2[4], c3[2];
    #pragma unroll
    for (int k = 0; k < 8; k++) c1[k] = p[2 * k] - p[2 * k + 1];
    #pragma unroll
    for (int k = 0; k < 4; k++) c2[k] = c1[2 * k] - c1[2 * k + 1];
    c3[0] = c2[0] - c2[1]; c3[1] = c2[2] - c2[3];
    float u0 = 0.0f, u1 = 0.0f;
    #pragma unroll
    for (int k = 0; k < 8; k++) u0 += c1[k];
    #pragma unroll
    for (int k = 0; k < 4; k++) u1 += c2[k];
    float u2 = c3[0] + c3[1];
    float t  = c3[0] - c3[1];     // full reg-parity term, seeds e3..e7

    // butterflies over g bits (within 16-lane sample group):
    // plain sums for u0..u2 (e0..e2); Walsh for t (e3..e7 at g=0,1,3,7,15)
    #pragma unroll
    for (int d = 1; d < 16; d <<= 1) {
        u0 += __shfl_xor_sync(FULL, u0, d);
        u1 += __shfl_xor_sync(FULL, u1, d);
        u2 += __shfl_xor_sync(FULL, u2, d);
        float pv = __shfl_xor_sync(FULL, t, d);
        t = (g & d) ? (pv - t) : (t + pv);
    }

    if (sample < batch) {
        float* o = out + sample * 8;
        if (g == 0) { o[0] = u0; o[1] = u1; o[2] = u2; o[3] = t; }
        else if ((g & (g + 1)) == 0)     // g = 1,3,7,15 -> qubits 4,5,6,7
            o[3 + __popc(g)] = t;
    }
}

extern "C" void kernel_launch(void* const* d_in, const int* in_sizes, int n_in,
                              void* d_out, int out_size) {
    const float* inputs = (const float*)d_in[0];   // [16384, 8] f32
    const float* theta  = (const float*)d_in[1];   // [2, 8, 3]  f32
    float* out = (float*)d_out;                    // [16384, 8] f32

    int batch = in_sizes[0] / 8;

    precompute_kernel<<<1, 256>>>(theta);

    int warps = (batch + 1) / 2;              // 2 samples per warp
    int threads = 256;                        // 8 warps / block
    int blocks = (warps * 32 + threads - 1) / threads;
    qsim_kernel<<<blocks, threads>>>(inputs, out, batch);
}

// round 9
// speedup vs baseline: 2.3264x; 1.0111x over previous
#include <cuda_runtime.h>

#define FULL 0xffffffffu
typedef unsigned long long u64;

// ---- f32x2 helpers (packed FP32; FFMA2 only reachable via PTX) ----
__device__ __forceinline__ u64 pk2(float lo, float hi) {
    u64 r; asm("mov.b64 %0, {%1, %2};" : "=l"(r) : "f"(lo), "f"(hi)); return r;
}
__device__ __forceinline__ void upk2(u64 v, float& lo, float& hi) {
    asm("mov.b64 {%0, %1}, %2;" : "=f"(lo), "=f"(hi) : "l"(v));
}
__device__ __forceinline__ u64 fma2(u64 a, u64 b, u64 c) {
    u64 d; asm("fma.rn.f32x2 %0, %1, %2, %3;" : "=l"(d) : "l"(a), "l"(b), "l"(c)); return d;
}
__device__ __forceinline__ u64 mul2(u64 a, u64 b) {
    u64 d; asm("mul.rn.f32x2 %0, %1, %2;" : "=l"(d) : "l"(a), "l"(b)); return d;
}
__device__ __forceinline__ u64 add2(u64 a, u64 b) {
    u64 d; asm("add.rn.f32x2 %0, %1, %2;" : "=l"(d) : "l"(a), "l"(b)); return d;
}
__device__ __forceinline__ u64 swap2(u64 v) {
    float lo, hi; upk2(v, lo, hi); return pk2(hi, lo);
}
// a - b  (one issue slot: fma with packed -1.0f)
#define NEG1_2 0xBF800000BF800000ULL
__device__ __forceinline__ u64 sub2(u64 a, u64 b) { return fma2(b, NEG1_2, a); }

// theta-derived tables. Amp index I: bit q = qubit q.
// qsim layout: I = (g<<4)|j, g = lane&15 (qubits 4..7), j = reg idx (qubits 0..3).
// Per-amp tables stored transposed [j*16+g] -> coalesced lane loads.
__device__ u64 g_ryc[16], g_rys[16], g_ryns[16];       // (c,c),(s,s),(-s,-s) per gate
__device__ __align__(16) u64 g_d0t[256];               // (cos phi, sin phi)
__device__ __align__(16) u64 g_d1x[256];               // (cos psi, cos psi)
__device__ __align__(16) u64 g_d1y[256];               // (-sin psi, +sin psi)

__global__ void precompute_kernel(const float* __restrict__ theta) {
    int I = threadIdx.x;          // amp index 0..255
    if (I < 16) {
        int layer = I >> 3, q = I & 7;
        float th = theta[layer * 24 + q * 3 + 1];
        float s, c;
        sincosf(0.5f * th, &s, &c);
        g_ryc[I]  = pk2(c, c);
        g_rys[I]  = pk2(s, s);
        g_ryns[I] = pk2(-s, -s);
    }
    int tslot = (I & 15) * 16 + (I >> 4);   // transposed slot

    // D0: RZ(phi) layer 0: bit=0 -> e^{-i phi/2}, bit=1 -> e^{+i phi/2}
    float a0 = 0.0f;
    #pragma unroll
    for (int q = 0; q < 8; q++) {
        float phi = theta[q * 3 + 0];
        a0 += ((I >> q) & 1) ? 0.5f * phi : -0.5f * phi;
    }
    float sr, cr;
    sincosf(a0, &sr, &cr);
    g_d0t[tslot] = pk2(cr, sr);

    // D1(K) = e^{i psi}, psi = Om0(src(K)) + Phi1(K), src(K) = K ^ ((K & 0x7F) << 1)
    int src = I ^ ((I & 0x7F) << 1);
    float a1 = 0.0f;
    #pragma unroll
    for (int q = 0; q < 8; q++) {
        float om0  = theta[q * 3 + 2];
        float phi1 = theta[24 + q * 3 + 0];
        a1 += ((src >> q) & 1) ? 0.5f * om0  : -0.5f * om0;
        a1 += ((I   >> q) & 1) ? 0.5f * phi1 : -0.5f * phi1;
    }
    sincosf(a1, &sr, &cr);
    g_d1x[tslot] = pk2(cr, cr);
    g_d1y[tslot] = pk2(-sr, sr);
    // RZ(om) of layer 1 dropped: no effect on probabilities.
}

// CNOT-perm step fused with D1, packed complex multiply:
// new = (dx*pr - dy*pi, dx*pi + dy*pr) = DX*p + DY*swap(p)
#define PERM_STEP(DST, SRC) { \
    int sl_ = slA ^ (((DST) >> 3) & 1); \
    u64 p_ = __shfl_sync(FULL, v[SRC], sl_); \
    v[DST] = fma2(d1yp[(DST) * 16], swap2(p_), mul2(d1xp[(DST) * 16], p_)); }

#define PERM_LAST(DST) { \
    int sl_ = slA ^ (((DST) >> 3) & 1); \
    u64 p_ = __shfl_sync(FULL, tv_, sl_); \
    v[DST] = fma2(d1yp[(DST) * 16], swap2(p_), mul2(d1xp[(DST) * 16], p_)); }

__global__ void __launch_bounds__(256)
qsim_kernel(const float* __restrict__ x, float* __restrict__ out, int batch) {
    int gw   = (int)((blockIdx.x * blockDim.x + threadIdx.x) >> 5);
    int lane = threadIdx.x & 31;
    int g    = lane & 15;          // lane-qubit bits (qubits 4..7)
    int base = lane & 16;          // sample selector
    int sample = gw * 2 + (lane >> 4);
    if (gw * 2 >= batch) return;
    int sidx = sample < batch ? sample : batch - 1;

    // ---- angle encoding ----
    float xv = x[sidx * 8 + (g & 7)];
    xv = fminf(1.0f, fmaxf(-1.0f, xv));
    float sv, cv;
    sincospif(0.5f * xv, &sv, &cv);

    float cq[8], sq[8];
    #pragma unroll
    for (int q = 0; q < 8; q++) {
        cq[q] = __shfl_sync(FULL, cv, base | q);
        sq[q] = __shfl_sync(FULL, sv, base | q);
    }
    // lane factor over qubits 4..7 (g bits 0..3)
    float lf = ((g & 1) ? sq[4] : cq[4]) * ((g & 2) ? sq[5] : cq[5])
             * ((g & 4) ? sq[6] : cq[6]) * ((g & 8) ? sq[7] : cq[7]);

    // real product over reg qubits 0..3
    float a0v = lf * cq[0], a1v = lf * sq[0];
    float t2[4], t3[8];
    #pragma unroll
    for (int j = 0; j < 4; j++)
        t2[j] = ((j & 1) ? a1v : a0v) * ((j & 2) ? sq[1] : cq[1]);
    #pragma unroll
    for (int j = 0; j < 8; j++)
        t3[j] = t2[j & 3] * ((j & 4) ? sq[2] : cq[2]);

    // packed state: v[j] = (ar, ai) = amp_j * (cos phi_j, sin phi_j)
    const u64* d0p = g_d0t + g;
    u64 v[16];
    #pragma unroll
    for (int j = 0; j < 16; j++) {
        float a = t3[j & 7] * ((j & 8) ? sq[3] : cq[3]);
        v[j] = mul2(pk2(a, a), d0p[j * 16]);
    }

    // CNOT perm: src lane (4-bit) = g ^ ((g&7)<<1), xor'd with dst reg bit 3
    const int slA = base | (g ^ ((g & 7) << 1));
    const u64* d1xp = g_d1x + g;
    const u64* d1yp = g_d1y + g;

    // ---- two layers of real RY gates (packed f32x2) + fused perm/diagonal ----
    #pragma unroll
    for (int layer = 0; layer < 2; layer++) {
        #pragma unroll
        for (int q = 0; q < 4; q++) {           // reg-qubit gates (in-lane)
            int gi = layer * 8 + q;
            u64 CG = g_ryc[gi], S = g_rys[gi], NS = g_ryns[gi];
            int m = 1 << q;
            #pragma unroll
            for (int j0 = 0; j0 < 16; j0++) {
                if (j0 & m) continue;
                int j1 = j0 | m;
                u64 b0 = v[j0], b1 = v[j1];
                v[j0] = fma2(NS, b1, mul2(CG, b0));
                v[j1] = fma2(S,  b0, mul2(CG, b1));
            }
        }
        #pragma unroll
        for (int q = 4; q < 8; q++) {           // lane-qubit gates
            int gi = layer * 8 + q;
            u64 CG = g_ryc[gi];
            int pb = 1 << (q - 4);
            u64 SS = (g & pb) ? g_rys[gi] : g_ryns[gi];
            #pragma unroll
            for (int j = 0; j < 16; j++) {
                u64 pv = __shfl_xor_sync(FULL, v[j], pb);
                v[j] = fma2(SS, pv, mul2(CG, v[j]));
            }
        }

        if (layer == 0) {
            // CNOT chain: new[I] = D1[I]*old[src(I)], src = I^((I&0x7F)<<1).
            // Reg part sigma(j)=j^((j&7)<<1): cycles (0)(8)(4 12)(1 3 5 15)(2 6 10 14)(7 9 11 13)
            PERM_STEP(0, 0)
            PERM_STEP(8, 8)
            { u64 tv_ = v[4];
              PERM_STEP(4, 12) PERM_LAST(12) }
            { u64 tv_ = v[1];
              PERM_STEP(1, 3) PERM_STEP(3, 5) PERM_STEP(5, 15) PERM_LAST(15) }
            { u64 tv_ = v[2];
              PERM_STEP(2, 6) PERM_STEP(6, 10) PERM_STEP(10, 14) PERM_LAST(14) }
            { u64 tv_ = v[7];
              PERM_STEP(7, 9) PERM_STEP(9, 11) PERM_STEP(11, 13) PERM_LAST(13) }
        }
        // layer 1: om-diag dropped; its CNOT chain folded into Walsh below.
    }

    // ---- measurement: e_q = sum_I (-1)^{parity(I & (2^{q+1}-1))} p_I ----
    // Packed cascade: halves carry (ar-part, ai-part); summed at the end.
    u64 p2[16];
    #pragma unroll
    for (int j = 0; j < 16; j++)
        p2[j] = mul2(v[j], v[j]);

    u64 c1[8], c2[4], c3[2];
    #pragma unroll
    for (int k = 0; k < 8; k++) c1[k] = sub2(p2[2 * k], p2[2 * k + 1]);
    #pragma unroll
    for (int k = 0; k < 4; k++) c2[k] = sub2(c1[2 * k], c1[2 * k + 1]);
    c3[0] = sub2(c2[0], c2[1]); c3[1] = sub2(c2[2], c2[3]);
    u64 u0p = add2(add2(add2(c1[0], c1[1]), add2(c1[2], c1[3])),
                   add2(add2(c1[4], c1[5]), add2(c1[6], c1[7])));
    u64 u1p = add2(add2(c2[0], c2[1]), add2(c2[2], c2[3]));
    u64 u2p = add2(c3[0], c3[1]);
    u64 tp  = sub2(c3[0], c3[1]);

    float lo, hi;
    upk2(u0p, lo, hi); float u0 = lo + hi;
    upk2(u1p, lo, hi); float u1 = lo + hi;
    upk2(u2p, lo, hi); float u2 = lo + hi;
    upk2(tp,  lo, hi); float t  = lo + hi;   // full reg-parity term, seeds e3..e7

    // butterflies over g bits (within 16-lane sample group):
    // plain sums for u0..u2 (e0..e2); Walsh for t (e3..e7 at g=0,1,3,7,15)
    #pragma unroll
    for (int d = 1; d < 16; d <<= 1) {
        u0 += __shfl_xor_sync(FULL, u0, d);
        u1 += __shfl_xor_sync(FULL, u1, d);
        u2 += __shfl_xor_sync(FULL, u2, d);
        float pv = __shfl_xor_sync(FULL, t, d);
        t = (g & d) ? (pv - t) : (t + pv);
    }

    if (sample < batch) {
        float* o = out + sample * 8;
        if (g == 0) { o[0] = u0; o[1] = u1; o[2] = u2; o[3] = t; }
        else if ((g & (g + 1)) == 0)     // g = 1,3,7,15 -> qubits 4,5,6,7
            o[3 + __popc(g)] = t;
    }
}

extern "C" void kernel_launch(void* const* d_in, const int* in_sizes, int n_in,
                              void* d_out, int out_size) {
    const float* inputs = (const float*)d_in[0];   // [16384, 8] f32
    const float* theta  = (const float*)d_in[1];   // [2, 8, 3]  f32
    float* out = (float*)d_out;                    // [16384, 8] f32

    int batch = in_sizes[0] / 8;

    precompute_kernel<<<1, 256>>>(theta);

    int warps = (batch + 1) / 2;              // 2 samples per warp
    int threads = 256;                        // 8 warps / block
    int blocks = (warps * 32 + threads - 1) / threads;
    qsim_kernel<<<blocks, threads>>>(inputs, out, batch);
}

// round 10
// speedup vs baseline: 2.5612x; 1.1009x over previous
#include <cuda_runtime.h>

#define FULL 0xffffffffu

// theta-derived tables (sample-independent). Amp index I: bit q = qubit q.
// qsim layout: I = (g<<4)|j, g = lane&15 (qubits 4..7), j = reg idx (qubits 0..3).
// Tables transposed [j*16+g] -> coalesced lane loads.
// Tangent-form gates: g_ryt[k] = tan(th_k/2); the product of all 16 cos(th_k/2)
// is folded into g_d0t, so gates cost 1 FMA/element.
__device__ float g_ryt[16];
__device__ __align__(16) float2 g_d0t[256];   // norm * (cos phi, sin phi)
__device__ __align__(16) float2 g_d1t[256];   // (cos psi, sin psi)

__global__ void precompute_kernel(const float* __restrict__ theta) {
    int I = threadIdx.x;          // amp index 0..255
    if (I < 16) {
        int layer = I >> 3, q = I & 7;
        float th = theta[layer * 24 + q * 3 + 1];
        g_ryt[I] = tanf(0.5f * th);
    }
    // global normalization: product of cos(th/2) over all 16 RY gates
    float norm = 1.0f;
    #pragma unroll
    for (int k = 0; k < 16; k++) {
        int layer = k >> 3, q = k & 7;
        norm *= cosf(0.5f * theta[layer * 24 + q * 3 + 1]);
    }

    int tslot = (I & 15) * 16 + (I >> 4);   // transposed slot

    // D0: RZ(phi) layer 0 diag (bit=0 -> -phi/2, bit=1 -> +phi/2), scaled by norm
    float a0 = 0.0f;
    #pragma unroll
    for (int q = 0; q < 8; q++) {
        float phi = theta[q * 3 + 0];
        a0 += ((I >> q) & 1) ? 0.5f * phi : -0.5f * phi;
    }
    float sr, cr;
    sincosf(a0, &sr, &cr);
    g_d0t[tslot] = make_float2(cr * norm, sr * norm);

    // D1(K) = e^{i psi}, psi = Om0(src(K)) + Phi1(K), src(K) = K ^ ((K & 0x7F) << 1)
    int src = I ^ ((I & 0x7F) << 1);
    float a1 = 0.0f;
    #pragma unroll
    for (int q = 0; q < 8; q++) {
        float om0  = theta[q * 3 + 2];
        float phi1 = theta[24 + q * 3 + 0];
        a1 += ((src >> q) & 1) ? 0.5f * om0  : -0.5f * om0;
        a1 += ((I   >> q) & 1) ? 0.5f * phi1 : -0.5f * phi1;
    }
    sincosf(a1, &sr, &cr);
    g_d1t[tslot] = make_float2(cr, sr);
    // RZ(om) of layer 1 dropped: no effect on probabilities.
}

// In-place CNOT-perm step fused with D1: new[DST] = D1[DST] * old[SRC]@srclane
#define PERM_STEP(DST, SRC) { \
    int sl_ = slA ^ (((DST) >> 3) & 1); \
    float pr_ = __shfl_sync(FULL, ar[SRC], sl_); \
    float pi_ = __shfl_sync(FULL, ai[SRC], sl_); \
    float2 d_ = d1p[(DST) * 16]; \
    ar[DST] = d_.x * pr_ - d_.y * pi_; \
    ai[DST] = d_.x * pi_ + d_.y * pr_; }

#define PERM_LAST(DST) { \
    int sl_ = slA ^ (((DST) >> 3) & 1); \
    float pr_ = __shfl_sync(FULL, tr_, sl_); \
    float pi_ = __shfl_sync(FULL, ti_, sl_); \
    float2 d_ = d1p[(DST) * 16]; \
    ar[DST] = d_.x * pr_ - d_.y * pi_; \
    ai[DST] = d_.x * pi_ + d_.y * pr_; }

__global__ void __launch_bounds__(256)
qsim_kernel(const float* __restrict__ x, float* __restrict__ out, int batch) {
    int gw   = (int)((blockIdx.x * blockDim.x + threadIdx.x) >> 5);
    int lane = threadIdx.x & 31;
    int g    = lane & 15;          // lane-qubit bits (qubits 4..7)
    int base = lane & 16;          // sample selector
    int sample = gw * 2 + (lane >> 4);
    if (gw * 2 >= batch) return;
    int sidx = sample < batch ? sample : batch - 1;

    // ---- angle encoding ----
    float xv = x[sidx * 8 + (g & 7)];
    xv = fminf(1.0f, fmaxf(-1.0f, xv));
    float sv, cv;
    sincospif(0.5f * xv, &sv, &cv);

    float cq[8], sq[8];
    #pragma unroll
    for (int q = 0; q < 8; q++) {
        cq[q] = __shfl_sync(FULL, cv, base | q);
        sq[q] = __shfl_sync(FULL, sv, base | q);
    }
    // lane factor over qubits 4..7 (g bits 0..3)
    float lf = ((g & 1) ? sq[4] : cq[4]) * ((g & 2) ? sq[5] : cq[5])
             * ((g & 4) ? sq[6] : cq[6]) * ((g & 8) ? sq[7] : cq[7]);

    // real product over reg qubits 0..3
    float a0v = lf * cq[0], a1v = lf * sq[0];
    float t2[4], t3[8], amp[16];
    #pragma unroll
    for (int j = 0; j < 4; j++)
        t2[j] = ((j & 1) ? a1v : a0v) * ((j & 2) ? sq[1] : cq[1]);
    #pragma unroll
    for (int j = 0; j < 8; j++)
        t3[j] = t2[j & 3] * ((j & 4) ? sq[2] : cq[2]);
    #pragma unroll
    for (int j = 0; j < 16; j++)
        amp[j] = t3[j & 7] * ((j & 8) ? sq[3] : cq[3]);

    // apply norm-scaled D0 (phi-diagonal of layer 0) -- coalesced loads
    const float2* d0p = g_d0t + g;
    float ar[16], ai[16];
    #pragma unroll
    for (int j = 0; j < 16; j++) {
        float2 d = d0p[j * 16];
        ar[j] = amp[j] * d.x;
        ai[j] = amp[j] * d.y;
    }

    // CNOT perm: src lane (4-bit) = g ^ ((g&7)<<1), xor'd with dst reg bit 3
    const int slA = base | (g ^ ((g & 7) << 1));
    const float2* d1p = g_d1t + g;

    // ---- two layers of tangent-form RY gates + fused perm/diagonal ----
    #pragma unroll
    for (int layer = 0; layer < 2; layer++) {
        #pragma unroll
        for (int q = 0; q < 4; q++) {           // reg-qubit gates: 1 FMA/element
            float tg = g_ryt[layer * 8 + q];
            int m = 1 << q;
            #pragma unroll
            for (int j0 = 0; j0 < 16; j0++) {
                if (j0 & m) continue;
                int j1 = j0 | m;
                float b0r = ar[j0], b0i = ai[j0];
                float b1r = ar[j1], b1i = ai[j1];
                ar[j0] = fmaf(-tg, b1r, b0r);
                ai[j0] = fmaf(-tg, b1i, b0i);
                ar[j1] = fmaf( tg, b0r, b1r);
                ai[j1] = fmaf( tg, b0i, b1i);
            }
        }
        #pragma unroll
        for (int q = 4; q < 8; q++) {           // lane-qubit gates: 1 FMA/element
            float tg = g_ryt[layer * 8 + q];
            int pb = 1 << (q - 4);
            float ss = (g & pb) ? tg : -tg;
            #pragma unroll
            for (int j = 0; j < 16; j++) {
                float pr = __shfl_xor_sync(FULL, ar[j], pb);
                float pi = __shfl_xor_sync(FULL, ai[j], pb);
                ar[j] = fmaf(ss, pr, ar[j]);
                ai[j] = fmaf(ss, pi, ai[j]);
            }
        }

        if (layer == 0) {
            // CNOT chain: new[I] = D1[I]*old[src(I)], src = I^((I&0x7F)<<1).
            // Reg part sigma(j)=j^((j&7)<<1): cycles (0)(8)(4 12)(1 3 5 15)(2 6 10 14)(7 9 11 13)
            PERM_STEP(0, 0)
            PERM_STEP(8, 8)
            { float tr_ = ar[4], ti_ = ai[4];
              PERM_STEP(4, 12) PERM_LAST(12) }
            { float tr_ = ar[1], ti_ = ai[1];
              PERM_STEP(1, 3) PERM_STEP(3, 5) PERM_STEP(5, 15) PERM_LAST(15) }
            { float tr_ = ar[2], ti_ = ai[2];
              PERM_STEP(2, 6) PERM_STEP(6, 10) PERM_STEP(10, 14) PERM_LAST(14) }
            { float tr_ = ar[7], ti_ = ai[7];
              PERM_STEP(7, 9) PERM_STEP(9, 11) PERM_STEP(11, 13) PERM_LAST(13) }
        }
        // layer 1: om-diag dropped; its CNOT chain folded into Walsh below.
    }

    // ---- measurement: e_q = sum_I (-1)^{parity(I & (2^{q+1}-1))} p_I ----
    float p[16];
    #pragma unroll
    for (int j = 0; j < 16; j++)
        p[j] = ar[j] * ar[j] + ai[j] * ai[j];

    // signed prefix-parity cascade over reg bits 0..3
    float c1[8], c2[4], c3[2];
    #pragma unroll
    for (int k = 0; k < 8; k++) c1[k] = p[2 * k] - p[2 * k + 1];
    #pragma unroll
    for (int k = 0; k < 4; k++) c2[k] = c1[2 * k] - c1[2 * k + 1];
    c3[0] = c2[0] - c2[1]; c3[1] = c2[2] - c2[3];
    float u0 = 0.0f, u1 = 0.0f;
    #pragma unroll
    for (int k = 0; k < 8; k++) u0 += c1[k];
    #pragma unroll
    for (int k = 0; k < 4; k++) u1 += c2[k];
    float u2 = c3[0] + c3[1];
    float t  = c3[0] - c3[1];     // full reg-parity term, seeds e3..e7

    // butterflies over g bits (within 16-lane sample group):
    // plain sums for u0..u2 (e0..e2); Walsh for t (e3..e7 at g=0,1,3,7,15)
    #pragma unroll
    for (int d = 1; d < 16; d <<= 1) {
        u0 += __shfl_xor_sync(FULL, u0, d);
        u1 += __shfl_xor_sync(FULL, u1, d);
        u2 += __shfl_xor_sync(FULL, u2, d);
        float pv = __shfl_xor_sync(FULL, t, d);
        t = (g & d) ? (pv - t) : (t + pv);
    }

    if (sample < batch) {
        float* o = out + sample * 8;
        if (g == 0) { o[0] = u0; o[1] = u1; o[2] = u2; o[3] = t; }
        else if ((g & (g + 1)) == 0)     // g = 1,3,7,15 -> qubits 4,5,6,7
            o[3 + __popc(g)] = t;
    }
}

extern "C" void kernel_launch(void* const* d_in, const int* in_sizes, int n_in,
                              void* d_out, int out_size) {
    const float* inputs = (const float*)d_in[0];   // [16384, 8] f32
    const float* theta  = (const float*)d_in[1];   // [2, 8, 3]  f32
    float* out = (float*)d_out;                    // [16384, 8] f32

    int batch = in_sizes[0] / 8;

    precompute_kernel<<<1, 256>>>(theta);

    int warps = (batch + 1) / 2;              // 2 samples per warp
    int threads = 256;                        // 8 warps / block
    int blocks = (warps * 32 + threads - 1) / threads;
    qsim_kernel<<<blocks, threads>>>(inputs, out, batch);
}